// round 1
// baseline (speedup 1.0000x reference)
#include <cuda_runtime.h>
#include <cstdint>
#include <cstddef>

#define T_STEPS 2048
#define H_DIM   512
#define B_DIM   32
#define D_IN    128
#define ALPHA   0.1f

// ---------------------------------------------------------------------------
// Kernel 1: x_proj GEMM.  C[M,N] = A[M,K] * B[N,K]^T
//   A = x  [65536, 128] row-major
//   B = I  [512, 128]   row-major
//   C = out [65536, 512] row-major  (later overwritten in-place by the scan)
// Tiling: BM=BN=64, BK=16, 256 threads, 4x4 micro-tile per thread.
// ---------------------------------------------------------------------------
#define BM 64
#define BN 64
#define BK 16

__global__ __launch_bounds__(256) void xproj_gemm(const float* __restrict__ A,
                                                  const float* __restrict__ B,
                                                  float* __restrict__ C) {
    __shared__ float As[BK][BM];   // transposed: [k][row]
    __shared__ float Bs[BK][BN];

    const int tid = threadIdx.x;
    const int bm  = blockIdx.x * BM;
    const int bn  = blockIdx.y * BN;

    // compute mapping: 16 x 16 thread grid, 4x4 outputs each
    const int tm = (tid & 15) * 4;   // row offset within tile
    const int tn = (tid >> 4) * 4;   // col offset within tile

    // load mapping: each thread loads one float4 per tile per operand
    const int lr = tid >> 2;         // row 0..63
    const int lc = (tid & 3) * 4;    // k offset 0,4,8,12

    const float* Ap = A + (size_t)(bm + lr) * D_IN + lc;
    const float* Bp = B + (size_t)(bn + lr) * D_IN + lc;

    float acc[4][4] = {};

    for (int k0 = 0; k0 < D_IN; k0 += BK) {
        const float4 av = *(const float4*)(Ap + k0);
        const float4 bv = *(const float4*)(Bp + k0);
        __syncthreads();   // protect previous iteration's reads
        As[lc + 0][lr] = av.x; As[lc + 1][lr] = av.y;
        As[lc + 2][lr] = av.z; As[lc + 3][lr] = av.w;
        Bs[lc + 0][lr] = bv.x; Bs[lc + 1][lr] = bv.y;
        Bs[lc + 2][lr] = bv.z; Bs[lc + 3][lr] = bv.w;
        __syncthreads();

        #pragma unroll
        for (int k = 0; k < BK; k++) {
            const float4 a = *(const float4*)&As[k][tm];
            const float4 b = *(const float4*)&Bs[k][tn];
            const float ar[4] = {a.x, a.y, a.z, a.w};
            const float br[4] = {b.x, b.y, b.z, b.w};
            #pragma unroll
            for (int i = 0; i < 4; i++)
                #pragma unroll
                for (int j = 0; j < 4; j++)
                    acc[i][j] = fmaf(ar[i], br[j], acc[i][j]);
        }
    }

    #pragma unroll
    for (int i = 0; i < 4; i++) {
        float4 v = make_float4(acc[i][0], acc[i][1], acc[i][2], acc[i][3]);
        *(float4*)(C + (size_t)(bm + tm + i) * H_DIM + bn + tn) = v;
    }
}

// ---------------------------------------------------------------------------
// Kernel 2: the sequential scan.  One CTA per batch, one thread per h element.
// out initially holds x_proj; each step reads xp[b][t][h] and overwrites it
// with h_t (same thread, same address -> safe in-place).
//
//   h_{t+1} = (1-a) h_t + a*(s0*m[h][0] + s1*m[h][1]) + a*xp_t
//   s_r     = sum_h tanh(h_t[h]) * n[h][r]          (rank-2 reduction)
// ---------------------------------------------------------------------------
__global__ __launch_bounds__(H_DIM) void rnn_scan(const float* __restrict__ m,
                                                  const float* __restrict__ n,
                                                  float* __restrict__ out) {
    const int b    = blockIdx.x;
    const int h    = threadIdx.x;
    const int lane = h & 31;
    const int wid  = h >> 5;

    __shared__ float2 part[2][16];   // double-buffered warp partials

    const float am0 = ALPHA * m[2 * h + 0];
    const float am1 = ALPHA * m[2 * h + 1];
    const float n0  = n[2 * h + 0];
    const float n1  = n[2 * h + 1];

    float* base = out + (size_t)b * T_STEPS * H_DIM + h;

    float hs = 0.0f;

    // prefetch pipeline (depth 4) for xp loads so DRAM latency stays off the
    // serial chain
    float xpb[4];
    #pragma unroll
    for (int i = 0; i < 4; i++) xpb[i] = base[(size_t)i * H_DIM];

    for (int t = 0; t < T_STEPS; t += 4) {
        #pragma unroll
        for (int u = 0; u < 4; u++) {
            const int tt = t + u;
            const float xp = xpb[u];
            if (tt + 4 < T_STEPS) xpb[u] = base[(size_t)(tt + 4) * H_DIM];

            float th;
            asm("tanh.approx.f32 %0, %1;" : "=f"(th) : "f"(hs));

            // part of the update that doesn't depend on the reduction —
            // computed while the shuffle tree is in flight
            const float hbase = fmaf(1.0f - ALPHA, hs, ALPHA * xp);

            float p0 = th * n0;
            float p1 = th * n1;
            #pragma unroll
            for (int o = 16; o; o >>= 1) {
                p0 += __shfl_xor_sync(0xffffffffu, p0, o);
                p1 += __shfl_xor_sync(0xffffffffu, p1, o);
            }

            const int par = tt & 1;
            if (lane == 0) part[par][wid] = make_float2(p0, p1);
            __syncthreads();

            float s0 = 0.0f, s1 = 0.0f;
            const float4* pp = (const float4*)&part[par][0];
            #pragma unroll
            for (int w = 0; w < 8; w++) {
                const float4 q = pp[w];
                s0 += q.x + q.z;
                s1 += q.y + q.w;
            }

            hs = fmaf(am0, s0, fmaf(am1, s1, hbase));
            base[(size_t)tt * H_DIM] = hs;
        }
    }
}

// ---------------------------------------------------------------------------
extern "C" void kernel_launch(void* const* d_in, const int* in_sizes, int n_in,
                              void* d_out, int out_size) {
    const float* x = (const float*)d_in[0];   // [32, 2048, 128]
    const float* m = (const float*)d_in[1];   // [512, 2]
    const float* n = (const float*)d_in[2];   // [512, 2]
    const float* I = (const float*)d_in[3];   // [512, 128]
    float* out = (float*)d_out;               // [32, 2048, 512]

    (void)in_sizes; (void)n_in; (void)out_size;

    dim3 ggrid((B_DIM * T_STEPS) / BM, H_DIM / BN);
    xproj_gemm<<<ggrid, 256>>>(x, I, out);
    rnn_scan<<<B_DIM, H_DIM>>>(m, n, out);
}